// round 1
// baseline (speedup 1.0000x reference)
#include <cuda_runtime.h>

// Problem constants
#define NN    4096          // n
#define DD    128           // d
#define TWO_N 8192
#define NWRD  128           // mask words per row = 4096/32
#define ZC    256           // Z columns = 2*d

// Scratch (static device globals — no runtime allocation)
__device__ float    g_s[NN];                 // dinv (shared top/bottom)
__device__ unsigned g_mask[NN * NWRD];       // binarized A as bits (2 MB)
__device__ float    g_Z[NN * ZC];            // scaled inputs  (4 MB)
__device__ float    g_U[TWO_N * DD];         // pre-weight hidden (4 MB)
__device__ float    g_stats[2 * DD];         // per-col sum / sumsq

// ---------------------------------------------------------------------------
// K1: binarize A -> bitmask, rowsum -> s[i] = rsqrt(rowsum+1)
// grid: 4096 blocks x 128 threads. Reads A once (64 MB), coalesced.
// ---------------------------------------------------------------------------
__global__ void k_mask(const float* __restrict__ A) {
    int row = blockIdx.x;
    int t = threadIdx.x;
    int w = t >> 5, l = t & 31;
    __shared__ int scnt[4];
    const float* arow = A + (size_t)row * NN;
    int cnt = 0;
    #pragma unroll 4
    for (int it = 0; it < 32; ++it) {
        float v = arow[it * 128 + t];
        bool one = (v > 0.0f);
        unsigned b = __ballot_sync(0xffffffffu, one);
        if (l == 0) g_mask[row * NWRD + it * 4 + w] = b;
        cnt += one ? 1 : 0;
    }
    #pragma unroll
    for (int o = 16; o; o >>= 1) cnt += __shfl_down_sync(0xffffffffu, cnt, o);
    if (l == 0) scnt[w] = cnt;
    __syncthreads();
    if (t == 0) {
        int c = scnt[0] + scnt[1] + scnt[2] + scnt[3];
        g_s[row] = rsqrtf((float)(c + 1));   // +1 from identity block
    }
}

// ---------------------------------------------------------------------------
// K2: Z[j, c] = s[j] * (c<128 ? x[j,c] : x[n+j, c-128]); also zero g_stats.
// grid: 4096 blocks x 256 threads.
// ---------------------------------------------------------------------------
__global__ void k_buildZ(const float* __restrict__ x) {
    int idx = blockIdx.x * 256 + threadIdx.x;   // 0 .. 4096*256-1
    if (blockIdx.x == 0 && threadIdx.x < 2 * DD) g_stats[threadIdx.x] = 0.0f;
    int j = idx >> 8;
    int c = idx & 255;
    float s = g_s[j];
    float v = (c < DD) ? x[j * DD + c] : x[(NN + j) * DD + (c - DD)];
    g_Z[idx] = s * v;
}

// ---------------------------------------------------------------------------
// K3: masked GEMM  Y = A_bin @ Z, fused epilogue -> U (adds identity/diag
// terms and final s_i scaling). 128 CTAs x 128 threads.
// CTA tile: 32 rows x 256 cols. 4 warps, each warp owns 8 rows; lane owns
// 8 cols (l, l+32, ..., l+224). Warp-uniform branch skips A_ij == 0
// (~50% of work). Z chunk (32 x 256 f32 = 32 KB) staged in shared.
// ---------------------------------------------------------------------------
#define KT 32
__global__ void k_spmm(const float* __restrict__ x) {
    __shared__ float Zs[KT][ZC];
    int t = threadIdx.x, w = t >> 5, l = t & 31;
    int rowBase = blockIdx.x * 32 + w * 8;

    float acc[8][8];
    #pragma unroll
    for (int r = 0; r < 8; ++r)
        #pragma unroll
        for (int q = 0; q < 8; ++q) acc[r][q] = 0.0f;

    for (int chunk = 0; chunk < NN / KT; ++chunk) {
        __syncthreads();   // previous chunk fully consumed
        // stage Z chunk: 8192 floats, 64 per thread, coalesced
        #pragma unroll 8
        for (int p = 0; p < 64; ++p) {
            int idx = t + p * 128;
            ((float*)Zs)[idx] = g_Z[chunk * (KT * ZC) + idx];
        }
        __syncthreads();

        unsigned m[8];
        #pragma unroll
        for (int r = 0; r < 8; ++r)
            m[r] = g_mask[(rowBase + r) * NWRD + chunk];   // uniform per warp

        for (int j = 0; j < 32; ++j) {
            float z[8];
            #pragma unroll
            for (int q = 0; q < 8; ++q) z[q] = Zs[j][l + 32 * q];
            #pragma unroll
            for (int r = 0; r < 8; ++r) {
                if ((m[r] >> j) & 1u) {          // warp-uniform branch
                    #pragma unroll
                    for (int q = 0; q < 8; ++q) acc[r][q] += z[q];
                }
            }
        }
    }

    // epilogue: U_top[i] = s_i*Y_top + s_i^2 * x[n+i];  U_bot likewise
    #pragma unroll
    for (int r = 0; r < 8; ++r) {
        int gi = rowBase + r;
        float s = g_s[gi];
        float s2 = s * s;
        #pragma unroll
        for (int q = 0; q < 8; ++q) {
            int c = l + 32 * q;
            float v = s * acc[r][q];
            if (c < DD) {
                g_U[gi * DD + c] = v + s2 * x[(NN + gi) * DD + c];
            } else {
                int cc = c - DD;
                g_U[(NN + gi) * DD + cc] = v + s2 * x[gi * DD + cc];
            }
        }
    }
}

// ---------------------------------------------------------------------------
// K4: H = U @ W, write pre-BN H to d_out, accumulate per-column sum/sumsq.
// 1024 CTAs x 256 threads; warp per row (8 rows/CTA), lane owns cols 4l..4l+3
// so W reads are one LDG.128 per warp per k.
// ---------------------------------------------------------------------------
__global__ void k_dense(const float* __restrict__ Wm, float* __restrict__ out) {
    __shared__ float Us[8][DD];
    __shared__ float sstat[2 * DD];
    int t = threadIdx.x, w = t >> 5, l = t & 31;
    int rowBase = blockIdx.x * 8;

    for (int p = t; p < 8 * DD; p += 256)
        ((float*)Us)[p] = g_U[rowBase * DD + p];
    sstat[t] = 0.0f;
    __syncthreads();

    const float4* W4 = (const float4*)Wm;
    float a0 = 0.f, a1 = 0.f, a2 = 0.f, a3 = 0.f;
    #pragma unroll 8
    for (int k = 0; k < DD; ++k) {
        float u = Us[w][k];
        float4 wv = W4[k * 32 + l];
        a0 += u * wv.x; a1 += u * wv.y; a2 += u * wv.z; a3 += u * wv.w;
    }
    int c0 = 4 * l;
    float4 hv = make_float4(a0, a1, a2, a3);
    ((float4*)out)[((rowBase + w) * DD + c0) >> 2] = hv;
    atomicAdd(&sstat[c0 + 0], a0);           atomicAdd(&sstat[DD + c0 + 0], a0 * a0);
    atomicAdd(&sstat[c0 + 1], a1);           atomicAdd(&sstat[DD + c0 + 1], a1 * a1);
    atomicAdd(&sstat[c0 + 2], a2);           atomicAdd(&sstat[DD + c0 + 2], a2 * a2);
    atomicAdd(&sstat[c0 + 3], a3);           atomicAdd(&sstat[DD + c0 + 3], a3 * a3);
    __syncthreads();
    atomicAdd(&g_stats[t], sstat[t]);
}

// ---------------------------------------------------------------------------
// K5: finalize BatchNorm (biased variance) + ReLU in place on d_out.
// ---------------------------------------------------------------------------
__global__ void k_bn(float* __restrict__ out,
                     const float* __restrict__ gamma,
                     const float* __restrict__ beta) {
    __shared__ float sscale[DD];
    __shared__ float sshift[DD];
    if (threadIdx.x < DD) {
        int c = threadIdx.x;
        float mean = g_stats[c] * (1.0f / (float)TWO_N);
        float var  = g_stats[DD + c] * (1.0f / (float)TWO_N) - mean * mean;
        float inv  = rsqrtf(var + 1e-5f);
        float g = gamma[c];
        sscale[c] = inv * g;
        sshift[c] = beta[c] - mean * inv * g;
    }
    __syncthreads();
    int idx = blockIdx.x * 256 + threadIdx.x;   // over 8192*128
    int c = idx & (DD - 1);
    float v = out[idx] * sscale[c] + sshift[c];
    out[idx] = fmaxf(v, 0.0f);
}

// ---------------------------------------------------------------------------
extern "C" void kernel_launch(void* const* d_in, const int* in_sizes, int n_in,
                              void* d_out, int out_size) {
    const float* x     = (const float*)d_in[0];   // [8192, 128]
    const float* A     = (const float*)d_in[1];   // [4096, 4096]
    const float* Wm    = (const float*)d_in[2];   // [128, 128]
    const float* gamma = (const float*)d_in[3];   // [128]
    const float* beta  = (const float*)d_in[4];   // [128]
    float* out = (float*)d_out;                   // [8192, 128]

    k_mask  <<<NN, 128>>>(A);
    k_buildZ<<<NN, 256>>>(x);
    k_spmm  <<<NN / 32, 128>>>(x);
    k_dense <<<TWO_N / 8, 256>>>(Wm, out);
    k_bn    <<<(TWO_N * DD) / 256, 256>>>(out, gamma, beta);
}

// round 3
// speedup vs baseline: 4.8239x; 4.8239x over previous
#include <cuda_runtime.h>
#include <cuda_bf16.h>
#include <cstdint>

#define NN    4096
#define DD    128
#define TWO_N 8192
#define ZC    256
#define NCH   64            // K chunks of 64
#define STG_BYTES 40960     // A 8KB + Bhi 16KB + Blo 16KB
#define SMEM_GEMM 81920

// ------------------------- device scratch -------------------------
__device__ __align__(16) __nv_bfloat16 g_Abf[(size_t)NN * NN];   // 32 MB row-major
__device__ __align__(16) __nv_bfloat16 g_Zhi[(size_t)NN * ZC];   // 2 MB  [K][N]
__device__ __align__(16) __nv_bfloat16 g_Zlo[(size_t)NN * ZC];   // 2 MB
__device__ __align__(16) float g_XW[(size_t)TWO_N * DD];         // 4 MB  x@W
__device__ float g_s[NN];
__device__ float g_stats[2 * DD];

// ------------------------- PTX helpers ----------------------------
__device__ __forceinline__ uint32_t smem_u32(const void* p) {
    uint32_t a;
    asm("{ .reg .u64 t; cvta.to.shared.u64 t, %1; cvt.u32.u64 %0, t; }" : "=r"(a) : "l"(p));
    return a;
}
#define CP16(dst, src) asm volatile("cp.async.cg.shared.global [%0], [%1], 16;" :: "r"(dst), "l"(src))
#define CP_COMMIT()    asm volatile("cp.async.commit_group;" ::: "memory")
#define CP_WAIT1()     asm volatile("cp.async.wait_group 1;" ::: "memory")
#define CP_WAIT0()     asm volatile("cp.async.wait_group 0;" ::: "memory")

#define LDSM4(r, a)  asm volatile("ldmatrix.sync.aligned.m8n8.x4.shared.b16 {%0,%1,%2,%3}, [%4];" \
    : "=r"((r)[0]),"=r"((r)[1]),"=r"((r)[2]),"=r"((r)[3]) : "r"(a))
#define LDSM4T(r, a) asm volatile("ldmatrix.sync.aligned.m8n8.x4.trans.shared.b16 {%0,%1,%2,%3}, [%4];" \
    : "=r"((r)[0]),"=r"((r)[1]),"=r"((r)[2]),"=r"((r)[3]) : "r"(a))

#define MMA(d, a, b0_, b1_) asm volatile( \
    "mma.sync.aligned.m16n8k16.row.col.f32.bf16.bf16.f32 " \
    "{%0,%1,%2,%3},{%4,%5,%6,%7},{%8,%9},{%0,%1,%2,%3};" \
    : "+f"((d)[0]),"+f"((d)[1]),"+f"((d)[2]),"+f"((d)[3]) \
    : "r"((a)[0]),"r"((a)[1]),"r"((a)[2]),"r"((a)[3]), "r"(b0_), "r"(b1_))

// ---------------------------------------------------------------------------
// K1: binarize A -> bf16 row-major (1.0/0.0 bit patterns), rowsum -> s.
// One row per block; thread handles 4 consecutive floats -> packed uint2 store.
// ---------------------------------------------------------------------------
__global__ void k_prep(const float* __restrict__ A) {
    int row = blockIdx.x, t = threadIdx.x, w = t >> 5, l = t & 31;
    __shared__ int scnt[4];
    if (row == 0 && t < 128) { g_stats[t] = 0.0f; g_stats[128 + t] = 0.0f; }
    const float4* ar4 = (const float4*)(A + (size_t)row * NN);
    uint2* dst = (uint2*)(g_Abf + (size_t)row * NN);
    int cnt = 0;
    #pragma unroll
    for (int it = 0; it < 8; ++it) {
        int i4 = it * 128 + t;
        float4 v = ar4[i4];
        unsigned b0 = (v.x > 0.f) ? 0x3F80u : 0u;
        unsigned b1 = (v.y > 0.f) ? 0x3F80u : 0u;
        unsigned b2 = (v.z > 0.f) ? 0x3F80u : 0u;
        unsigned b3 = (v.w > 0.f) ? 0x3F80u : 0u;
        cnt += (b0 ? 1 : 0) + (b1 ? 1 : 0) + (b2 ? 1 : 0) + (b3 ? 1 : 0);
        uint2 pk; pk.x = b0 | (b1 << 16); pk.y = b2 | (b3 << 16);
        dst[i4] = pk;
    }
    #pragma unroll
    for (int o = 16; o; o >>= 1) cnt += __shfl_down_sync(0xffffffffu, cnt, o);
    if (l == 0) scnt[w] = cnt;
    __syncthreads();
    if (t == 0)
        g_s[row] = rsqrtf((float)(scnt[0] + scnt[1] + scnt[2] + scnt[3] + 1));
}

// ---------------------------------------------------------------------------
// K2: xw = x @ W   [8192,128]@[128,128].  128 CTAs x 256 thr, 64 rows/CTA.
// ---------------------------------------------------------------------------
__global__ void k_xw(const float* __restrict__ x, const float* __restrict__ W) {
    __shared__ float xs[64][128];
    int t = threadIdx.x, w = t >> 5, l = t & 31;
    int rb = blockIdx.x * 64;
    const float4* xin = (const float4*)(x + (size_t)rb * DD);
    float4* xs4 = (float4*)xs;
    #pragma unroll
    for (int i = 0; i < 8; ++i) xs4[t + i * 256] = xin[t + i * 256];
    __syncthreads();
    const float4* W4 = (const float4*)W;
    float acc[8][4];
    #pragma unroll
    for (int i = 0; i < 8; ++i) { acc[i][0]=0.f; acc[i][1]=0.f; acc[i][2]=0.f; acc[i][3]=0.f; }
    #pragma unroll 4
    for (int k = 0; k < DD; ++k) {
        float4 wv = W4[k * 32 + l];
        #pragma unroll
        for (int i = 0; i < 8; ++i) {
            float u = xs[w * 8 + i][k];
            acc[i][0] += u * wv.x; acc[i][1] += u * wv.y;
            acc[i][2] += u * wv.z; acc[i][3] += u * wv.w;
        }
    }
    #pragma unroll
    for (int i = 0; i < 8; ++i) {
        float4 v = make_float4(acc[i][0], acc[i][1], acc[i][2], acc[i][3]);
        *(float4*)&g_XW[(size_t)(rb + w * 8 + i) * DD + 4 * l] = v;
    }
}

// ---------------------------------------------------------------------------
// K3: Z[j][c] = s_j * (c<128 ? xw[j][c] : xw[NN+j][c-128]) as bf16 hi + lo.
// Thread per column-pair. 2048 x 256.
// ---------------------------------------------------------------------------
__global__ void k_zt() {
    int idx = blockIdx.x * 256 + threadIdx.x;  // 0 .. 512K-1
    int j  = idx >> 7;
    int c2 = (idx & 127) * 2;
    float s = g_s[j];
    const float* src = (c2 < DD) ? &g_XW[(size_t)j * DD + c2]
                                 : &g_XW[(size_t)(NN + j) * DD + (c2 - DD)];
    float2 v = *(const float2*)src;
    float z0 = s * v.x, z1 = s * v.y;
    __nv_bfloat16 h0 = __float2bfloat16(z0);
    __nv_bfloat16 h1 = __float2bfloat16(z1);
    __nv_bfloat16 l0 = __float2bfloat16(z0 - __bfloat162float(h0));
    __nv_bfloat16 l1 = __float2bfloat16(z1 - __bfloat162float(h1));
    unsigned hp = (unsigned)__bfloat16_as_ushort(h0) | ((unsigned)__bfloat16_as_ushort(h1) << 16);
    unsigned lp = (unsigned)__bfloat16_as_ushort(l0) | ((unsigned)__bfloat16_as_ushort(l1) << 16);
    *(unsigned*)&g_Zhi[(size_t)j * ZC + c2] = hp;
    *(unsigned*)&g_Zlo[(size_t)j * ZC + c2] = lp;
}

// ---------------------------------------------------------------------------
// K4: Y = A_bin @ Z via mma.sync bf16 (hi+lo into same fp32 accum).
// CTA 64x128, 256 thr, 8 warps: warp tile 32x64, K-split x2 (kg=wid>>2).
// 2-stage cp.async pipeline. Fused epilogue: s_i scale + diag + BN stats.
// ---------------------------------------------------------------------------
__global__ void __launch_bounds__(256, 1) k_gemm(float* __restrict__ out) {
    extern __shared__ char smem[];
    uint32_t sb = smem_u32(smem);
    int t = threadIdx.x, wid = t >> 5, lid = t & 31;
    int wm = wid & 1, wn = (wid >> 1) & 1, kg = wid >> 2;
    int mbase = blockIdx.x * 64;
    int nbg   = blockIdx.y * 128;
    const __nv_bfloat16* Ag = g_Abf + (size_t)mbase * NN;

    auto issue = [&](int c, int st) {
        uint32_t sa = sb + st * STG_BYTES;
        uint32_t bh = sa + 8192, bl = sa + 24576;
        #pragma unroll
        for (int p = 0; p < 2; ++p) {             // A: 64x64 bf16
            int idx = t + p * 256;
            int r = idx >> 3, ch = idx & 7;
            uint32_t d = sa + r * 128 + ((ch ^ (r & 7)) << 4);
            CP16(d, (const char*)(Ag + (size_t)r * NN + c * 64 + ch * 8));
        }
        #pragma unroll
        for (int p = 0; p < 4; ++p) {             // B hi/lo: 64x128 bf16 each
            int idx = t + p * 256;
            int k = idx >> 4, ch = idx & 15;
            uint32_t off = k * 256 + ((ch ^ (k & 7)) << 4);
            size_t ge = (size_t)(c * 64 + k) * ZC + nbg + ch * 8;
            CP16(bh + off, (const char*)(g_Zhi + ge));
            CP16(bl + off, (const char*)(g_Zlo + ge));
        }
        CP_COMMIT();
    };

    float acc[2][8][4];
    #pragma unroll
    for (int mi = 0; mi < 2; ++mi)
        #pragma unroll
        for (int nj = 0; nj < 8; ++nj)
            #pragma unroll
            for (int q = 0; q < 4; ++q) acc[mi][nj][q] = 0.0f;

    issue(0, 0); issue(1, 1);

    int m0 = wm * 32, nb0 = wn * 64;

    for (int c = 0; c < NCH; ++c) {
        int st = c & 1;
        if (c == NCH - 1) { CP_WAIT0(); } else { CP_WAIT1(); }
        __syncthreads();
        uint32_t sa = sb + st * STG_BYTES;
        uint32_t bhb = sa + 8192, blb = sa + 24576;
        #pragma unroll
        for (int kk2 = 0; kk2 < 2; ++kk2) {
            int kk = kg * 2 + kk2;
            uint32_t af[2][4];
            #pragma unroll
            for (int mi = 0; mi < 2; ++mi) {
                int row = m0 + mi * 16 + (lid & 15);
                int ch  = kk * 2 + (lid >> 4);
                LDSM4(af[mi], sa + row * 128 + ((ch ^ (row & 7)) << 4));
            }
            int kb = kk * 16 + (lid & 7) + (((lid >> 3) & 1) << 3);
            int cb = (lid >> 4);
            uint32_t bf[8][2];
            #pragma unroll
            for (int np = 0; np < 4; ++np) {      // B hi
                int ch = ((nb0 + np * 16) >> 3) + cb;
                uint32_t r[4];
                LDSM4T(r, bhb + kb * 256 + ((ch ^ (kb & 7)) << 4));
                bf[np*2][0]=r[0]; bf[np*2][1]=r[1]; bf[np*2+1][0]=r[2]; bf[np*2+1][1]=r[3];
            }
            #pragma unroll
            for (int mi = 0; mi < 2; ++mi)
                #pragma unroll
                for (int nj = 0; nj < 8; ++nj)
                    MMA(acc[mi][nj], af[mi], bf[nj][0], bf[nj][1]);
            #pragma unroll
            for (int np = 0; np < 4; ++np) {      // B lo
                int ch = ((nb0 + np * 16) >> 3) + cb;
                uint32_t r[4];
                LDSM4T(r, blb + kb * 256 + ((ch ^ (kb & 7)) << 4));
                bf[np*2][0]=r[0]; bf[np*2][1]=r[1]; bf[np*2+1][0]=r[2]; bf[np*2+1][1]=r[3];
            }
            #pragma unroll
            for (int mi = 0; mi < 2; ++mi)
                #pragma unroll
                for (int nj = 0; nj < 8; ++nj)
                    MMA(acc[mi][nj], af[mi], bf[nj][0], bf[nj][1]);
        }
        __syncthreads();
        if (c + 2 < NCH) issue(c + 2, st);
    }

    // ---- K-split reduction through smem (padded stride 129) ----
    __syncthreads();
    float* red = (float*)smem;
    float* sstat = (float*)(smem + 36864);
    int grp = lid >> 2, qp = lid & 3;
    sstat[t] = 0.0f;
    if (kg == 1) {
        #pragma unroll
        for (int mi = 0; mi < 2; ++mi)
            #pragma unroll
            for (int nj = 0; nj < 8; ++nj) {
                int r0 = m0 + mi * 16 + grp;
                int c0 = nb0 + nj * 8 + qp * 2;
                red[r0 * 129 + c0]       = acc[mi][nj][0];
                red[r0 * 129 + c0 + 1]   = acc[mi][nj][1];
                red[(r0+8) * 129 + c0]   = acc[mi][nj][2];
                red[(r0+8) * 129 + c0+1] = acc[mi][nj][3];
            }
    }
    __syncthreads();
    if (kg == 0) {
        #pragma unroll
        for (int mi = 0; mi < 2; ++mi) {
            int gi0 = mbase + m0 + mi * 16 + grp;
            int gi1 = gi0 + 8;
            float s0 = g_s[gi0], s1 = g_s[gi1];
            float s0q = s0 * s0, s1q = s1 * s1;
            #pragma unroll
            for (int nj = 0; nj < 8; ++nj) {
                int r0 = m0 + mi * 16 + grp;
                int c0 = nb0 + nj * 8 + qp * 2;
                float y00 = acc[mi][nj][0] + red[r0 * 129 + c0];
                float y01 = acc[mi][nj][1] + red[r0 * 129 + c0 + 1];
                float y10 = acc[mi][nj][2] + red[(r0+8) * 129 + c0];
                float y11 = acc[mi][nj][3] + red[(r0+8) * 129 + c0 + 1];
                int C = nbg + c0;
                int orow0, orow1, oc, drow0, drow1;
                if (C < DD) { orow0 = gi0; orow1 = gi1; oc = C;      drow0 = NN + gi0; drow1 = NN + gi1; }
                else        { orow0 = NN + gi0; orow1 = NN + gi1; oc = C - DD; drow0 = gi0; drow1 = gi1; }
                float2 d0 = *(const float2*)&g_XW[(size_t)drow0 * DD + oc];
                float2 d1 = *(const float2*)&g_XW[(size_t)drow1 * DD + oc];
                float h00 = s0 * y00 + s0q * d0.x;
                float h01 = s0 * y01 + s0q * d0.y;
                float h10 = s1 * y10 + s1q * d1.x;
                float h11 = s1 * y11 + s1q * d1.y;
                *(float2*)&out[(size_t)orow0 * DD + oc] = make_float2(h00, h01);
                *(float2*)&out[(size_t)orow1 * DD + oc] = make_float2(h10, h11);
                float v0 = h00 + h10, v1 = h01 + h11;
                float w0 = h00*h00 + h10*h10, w1 = h01*h01 + h11*h11;
                #pragma unroll
                for (int o = 16; o >= 4; o >>= 1) {
                    v0 += __shfl_xor_sync(0xffffffffu, v0, o);
                    v1 += __shfl_xor_sync(0xffffffffu, v1, o);
                    w0 += __shfl_xor_sync(0xffffffffu, w0, o);
                    w1 += __shfl_xor_sync(0xffffffffu, w1, o);
                }
                if (grp == 0) {
                    int cs = C & (DD - 1);
                    atomicAdd(&sstat[cs], v0);
                    atomicAdd(&sstat[cs + 1], v1);
                    atomicAdd(&sstat[DD + cs], w0);
                    atomicAdd(&sstat[DD + cs + 1], w1);
                }
            }
        }
    }
    __syncthreads();
    atomicAdd(&g_stats[t], sstat[t]);
}

// ---------------------------------------------------------------------------
// K5: finalize BatchNorm (biased var) + ReLU in place
// ---------------------------------------------------------------------------
__global__ void k_bn(float* __restrict__ out,
                     const float* __restrict__ gamma,
                     const float* __restrict__ beta) {
    __shared__ float sscale[DD], sshift[DD];
    if (threadIdx.x < DD) {
        int c = threadIdx.x;
        float mean = g_stats[c] * (1.0f / (float)TWO_N);
        float var  = g_stats[DD + c] * (1.0f / (float)TWO_N) - mean * mean;
        float inv  = rsqrtf(var + 1e-5f);
        float g = gamma[c];
        sscale[c] = inv * g;
        sshift[c] = beta[c] - mean * inv * g;
    }
    __syncthreads();
    int idx = blockIdx.x * 256 + threadIdx.x;
    int c = idx & (DD - 1);
    float v = out[idx] * sscale[c] + sshift[c];
    out[idx] = fmaxf(v, 0.0f);
}

// ---------------------------------------------------------------------------
extern "C" void kernel_launch(void* const* d_in, const int* in_sizes, int n_in,
                              void* d_out, int out_size) {
    const float* x     = (const float*)d_in[0];   // [8192, 128]
    const float* A     = (const float*)d_in[1];   // [4096, 4096]
    const float* Wm    = (const float*)d_in[2];   // [128, 128]
    const float* gamma = (const float*)d_in[3];   // [128]
    const float* beta  = (const float*)d_in[4];   // [128]
    float* out = (float*)d_out;                   // [8192, 128]

    cudaFuncSetAttribute(k_gemm, cudaFuncAttributeMaxDynamicSharedMemorySize, SMEM_GEMM);

    k_prep<<<NN, 128>>>(A);
    k_xw  <<<TWO_N / 64, 256>>>(x, Wm);
    k_zt  <<<2048, 256>>>();
    dim3 gg(NN / 64, 2);
    k_gemm<<<gg, 256, SMEM_GEMM>>>(out);
    k_bn  <<<(TWO_N * DD) / 256, 256>>>(out, gamma, beta);
}

// round 4
// speedup vs baseline: 4.9691x; 1.0301x over previous
#include <cuda_runtime.h>
#include <cuda_bf16.h>
#include <cstdint>

#define NN    4096
#define DD    128
#define TWO_N 8192
#define ZC    256
#define KSPLIT 4
#define KPER  (NN / KSPLIT)      // 1024 per CTA
#define KC    64                 // K chunk
#define NCHC  (KPER / KC)        // 16 chunks per CTA
#define STG_BYTES 49152          // A 16KB + Bhi 16KB + Blo 16KB
#define SMEM_GEMM (2 * STG_BYTES)   // 98304

// ------------------------- device scratch -------------------------
__device__ __align__(16) __nv_bfloat16 g_Abf[(size_t)NN * NN];   // 32 MB row-major
__device__ __align__(16) __nv_bfloat16 g_Zhi[(size_t)NN * ZC];   // 2 MB  [K][N]
__device__ __align__(16) __nv_bfloat16 g_Zlo[(size_t)NN * ZC];   // 2 MB
__device__ __align__(16) float g_XW[(size_t)TWO_N * DD];         // 4 MB  x@W
__device__ __align__(16) float g_Yp[KSPLIT][(size_t)NN * ZC];    // 16 MB partials
__device__ float g_s[NN];
__device__ float g_stats[2 * DD];

// ------------------------- PTX helpers ----------------------------
__device__ __forceinline__ uint32_t smem_u32(const void* p) {
    uint32_t a;
    asm("{ .reg .u64 t; cvta.to.shared.u64 t, %1; cvt.u32.u64 %0, t; }" : "=r"(a) : "l"(p));
    return a;
}
#define CP16(dst, src) asm volatile("cp.async.cg.shared.global [%0], [%1], 16;" :: "r"(dst), "l"(src))
#define CP_COMMIT()    asm volatile("cp.async.commit_group;" ::: "memory")
#define CP_WAIT1()     asm volatile("cp.async.wait_group 1;" ::: "memory")

#define LDSM4(r, a)  asm volatile("ldmatrix.sync.aligned.m8n8.x4.shared.b16 {%0,%1,%2,%3}, [%4];" \
    : "=r"((r)[0]),"=r"((r)[1]),"=r"((r)[2]),"=r"((r)[3]) : "r"(a))
#define LDSM4T(r, a) asm volatile("ldmatrix.sync.aligned.m8n8.x4.trans.shared.b16 {%0,%1,%2,%3}, [%4];" \
    : "=r"((r)[0]),"=r"((r)[1]),"=r"((r)[2]),"=r"((r)[3]) : "r"(a))

#define MMA(d, a, b0_, b1_) asm volatile( \
    "mma.sync.aligned.m16n8k16.row.col.f32.bf16.bf16.f32 " \
    "{%0,%1,%2,%3},{%4,%5,%6,%7},{%8,%9},{%0,%1,%2,%3};" \
    : "+f"((d)[0]),"+f"((d)[1]),"+f"((d)[2]),"+f"((d)[3]) \
    : "r"((a)[0]),"r"((a)[1]),"r"((a)[2]),"r"((a)[3]), "r"(b0_), "r"(b1_))

// ---------------------------------------------------------------------------
// K1: binarize A -> bf16 row-major, rowsum -> s, zero stats.
// ---------------------------------------------------------------------------
__global__ void k_prep(const float* __restrict__ A) {
    int row = blockIdx.x, t = threadIdx.x, w = t >> 5, l = t & 31;
    __shared__ int scnt[4];
    if (row == 0 && t < 128) { g_stats[t] = 0.0f; g_stats[128 + t] = 0.0f; }
    const float4* ar4 = (const float4*)(A + (size_t)row * NN);
    uint2* dst = (uint2*)(g_Abf + (size_t)row * NN);
    int cnt = 0;
    #pragma unroll
    for (int it = 0; it < 8; ++it) {
        int i4 = it * 128 + t;
        float4 v = ar4[i4];
        unsigned b0 = (v.x > 0.f) ? 0x3F80u : 0u;
        unsigned b1 = (v.y > 0.f) ? 0x3F80u : 0u;
        unsigned b2 = (v.z > 0.f) ? 0x3F80u : 0u;
        unsigned b3 = (v.w > 0.f) ? 0x3F80u : 0u;
        cnt += (b0 ? 1 : 0) + (b1 ? 1 : 0) + (b2 ? 1 : 0) + (b3 ? 1 : 0);
        uint2 pk; pk.x = b0 | (b1 << 16); pk.y = b2 | (b3 << 16);
        dst[i4] = pk;
    }
    #pragma unroll
    for (int o = 16; o; o >>= 1) cnt += __shfl_down_sync(0xffffffffu, cnt, o);
    if (l == 0) scnt[w] = cnt;
    __syncthreads();
    if (t == 0)
        g_s[row] = rsqrtf((float)(scnt[0] + scnt[1] + scnt[2] + scnt[3] + 1));
}

// ---------------------------------------------------------------------------
// K2: fused xw = x@W AND Z build. CTA handles j0..j0+31 (x rows j and NN+j).
// Writes g_XW (fp32, for diag) and Zhi/Zlo rows directly (no transpose needed:
// Z[j][0:128] from top row j, Z[j][128:256] from bottom row NN+j).
// ---------------------------------------------------------------------------
__global__ void k_xw2(const float* __restrict__ x, const float* __restrict__ W) {
    __shared__ float xs[64][128];
    int t = threadIdx.x, w = t >> 5, l = t & 31;
    int j0 = blockIdx.x * 32;
    // rows 0-31: x[j0..], rows 32-63: x[NN+j0..]
    const float4* xt = (const float4*)(x + (size_t)j0 * DD);
    const float4* xb = (const float4*)(x + (size_t)(NN + j0) * DD);
    float4* xs4 = (float4*)xs;
    #pragma unroll
    for (int i = 0; i < 4; ++i) xs4[t + i * 256] = xt[t + i * 256];
    #pragma unroll
    for (int i = 0; i < 4; ++i) xs4[1024 + t + i * 256] = xb[t + i * 256];
    __syncthreads();
    const float4* W4 = (const float4*)W;
    float acc[8][4];
    #pragma unroll
    for (int i = 0; i < 8; ++i) { acc[i][0]=0.f; acc[i][1]=0.f; acc[i][2]=0.f; acc[i][3]=0.f; }
    #pragma unroll 4
    for (int k = 0; k < DD; ++k) {
        float4 wv = W4[k * 32 + l];
        #pragma unroll
        for (int i = 0; i < 8; ++i) {
            float u = xs[w * 8 + i][k];
            acc[i][0] += u * wv.x; acc[i][1] += u * wv.y;
            acc[i][2] += u * wv.z; acc[i][3] += u * wv.w;
        }
    }
    #pragma unroll
    for (int i = 0; i < 8; ++i) {
        int r = w * 8 + i;                 // local row
        int top = (r < 32);
        int j = j0 + (r & 31);
        int grow = top ? j : (NN + j);
        float4 v = make_float4(acc[i][0], acc[i][1], acc[i][2], acc[i][3]);
        *(float4*)&g_XW[(size_t)grow * DD + 4 * l] = v;
        float s = g_s[j];
        float z0 = s * v.x, z1 = s * v.y, z2 = s * v.z, z3 = s * v.w;
        __nv_bfloat16 h0 = __float2bfloat16(z0), h1 = __float2bfloat16(z1);
        __nv_bfloat16 h2 = __float2bfloat16(z2), h3 = __float2bfloat16(z3);
        __nv_bfloat16 e0 = __float2bfloat16(z0 - __bfloat162float(h0));
        __nv_bfloat16 e1 = __float2bfloat16(z1 - __bfloat162float(h1));
        __nv_bfloat16 e2 = __float2bfloat16(z2 - __bfloat162float(h2));
        __nv_bfloat16 e3 = __float2bfloat16(z3 - __bfloat162float(h3));
        uint2 hp, lp;
        hp.x = (unsigned)__bfloat16_as_ushort(h0) | ((unsigned)__bfloat16_as_ushort(h1) << 16);
        hp.y = (unsigned)__bfloat16_as_ushort(h2) | ((unsigned)__bfloat16_as_ushort(h3) << 16);
        lp.x = (unsigned)__bfloat16_as_ushort(e0) | ((unsigned)__bfloat16_as_ushort(e1) << 16);
        lp.y = (unsigned)__bfloat16_as_ushort(e2) | ((unsigned)__bfloat16_as_ushort(e3) << 16);
        int coff = (top ? 0 : DD) + 4 * l;
        *(uint2*)&g_Zhi[(size_t)j * ZC + coff] = hp;
        *(uint2*)&g_Zlo[(size_t)j * ZC + coff] = lp;
    }
}

// ---------------------------------------------------------------------------
// K3: GEMM partials. grid (32, 2, 4): 128x128 CTA tile, K-split/4 over grid.z.
// 2 CTAs/SM. 8 warps, warp tile 32x64. 2-stage cp.async, always-commit trick.
// ---------------------------------------------------------------------------
__global__ void __launch_bounds__(256, 2) k_gemm() {
    extern __shared__ char smem[];
    uint32_t sb = smem_u32(smem);
    int t = threadIdx.x, wid = t >> 5, lid = t & 31;
    int wm = wid & 3, wn = wid >> 2;
    int m0 = wm * 32, nb0 = wn * 64;
    int mbase = blockIdx.x * 128;
    int nbg   = blockIdx.y * 128;
    int kbase = blockIdx.z * KPER;
    const __nv_bfloat16* Ag = g_Abf + (size_t)mbase * NN + kbase;
    const __nv_bfloat16* Bh = g_Zhi + (size_t)kbase * ZC + nbg;
    const __nv_bfloat16* Bl = g_Zlo + (size_t)kbase * ZC + nbg;

    auto issue = [&](int c) {
        if (c < NCHC) {
            uint32_t sa = sb + (c & 1) * STG_BYTES;
            uint32_t bh = sa + 16384, bl = sa + 32768;
            #pragma unroll
            for (int p = 0; p < 4; ++p) {            // A: 128x64 bf16, 128B rows
                int idx = t + p * 256;
                int r = idx >> 3, ch = idx & 7;
                uint32_t d = sa + r * 128 + ((ch ^ (r & 7)) << 4);
                CP16(d, (const char*)(Ag + (size_t)r * NN + c * KC + ch * 8));
            }
            #pragma unroll
            for (int p = 0; p < 4; ++p) {            // Bhi: 64x128 bf16, 256B rows
                int idx = t + p * 256;
                int k = idx >> 4, ch = idx & 15;
                uint32_t off = k * 256 + ((ch ^ (k & 7)) << 4);
                CP16(bh + off, (const char*)(Bh + (size_t)(c * KC + k) * ZC + ch * 8));
            }
            #pragma unroll
            for (int p = 0; p < 4; ++p) {            // Blo
                int idx = t + p * 256;
                int k = idx >> 4, ch = idx & 15;
                uint32_t off = k * 256 + ((ch ^ (k & 7)) << 4);
                CP16(bl + off, (const char*)(Bl + (size_t)(c * KC + k) * ZC + ch * 8));
            }
        }
        CP_COMMIT();
    };

    float acc[2][8][4];
    #pragma unroll
    for (int mi = 0; mi < 2; ++mi)
        #pragma unroll
        for (int nj = 0; nj < 8; ++nj)
            #pragma unroll
            for (int q = 0; q < 4; ++q) acc[mi][nj][q] = 0.0f;

    issue(0); issue(1);

    for (int c = 0; c < NCHC; ++c) {
        CP_WAIT1();                  // groups {c, c+1} pending -> c complete
        __syncthreads();
        uint32_t sa = sb + (c & 1) * STG_BYTES;
        uint32_t bhb = sa + 16384, blb = sa + 32768;
        #pragma unroll
        for (int kk = 0; kk < 4; ++kk) {
            uint32_t af[2][4];
            #pragma unroll
            for (int mi = 0; mi < 2; ++mi) {
                int row = m0 + mi * 16 + (lid & 15);
                int ch  = kk * 2 + (lid >> 4);
                LDSM4(af[mi], sa + row * 128 + ((ch ^ (row & 7)) << 4));
            }
            int kb = kk * 16 + (lid & 15);
            int cb = lid >> 4;
            uint32_t bf[8][2];
            #pragma unroll
            for (int np = 0; np < 4; ++np) {         // hi
                int ch = (nb0 >> 3) + np * 2 + cb;
                uint32_t r[4];
                LDSM4T(r, bhb + kb * 256 + ((ch ^ (kb & 7)) << 4));
                bf[np*2][0]=r[0]; bf[np*2][1]=r[1]; bf[np*2+1][0]=r[2]; bf[np*2+1][1]=r[3];
            }
            #pragma unroll
            for (int mi = 0; mi < 2; ++mi)
                #pragma unroll
                for (int nj = 0; nj < 8; ++nj)
                    MMA(acc[mi][nj], af[mi], bf[nj][0], bf[nj][1]);
            #pragma unroll
            for (int np = 0; np < 4; ++np) {         // lo
                int ch = (nb0 >> 3) + np * 2 + cb;
                uint32_t r[4];
                LDSM4T(r, blb + kb * 256 + ((ch ^ (kb & 7)) << 4));
                bf[np*2][0]=r[0]; bf[np*2][1]=r[1]; bf[np*2+1][0]=r[2]; bf[np*2+1][1]=r[3];
            }
            #pragma unroll
            for (int mi = 0; mi < 2; ++mi)
                #pragma unroll
                for (int nj = 0; nj < 8; ++nj)
                    MMA(acc[mi][nj], af[mi], bf[nj][0], bf[nj][1]);
        }
        __syncthreads();
        issue(c + 2);
    }

    // write partial tile to g_Yp[bz]
    float* Yp = g_Yp[blockIdx.z];
    int grp = lid >> 2, qp = lid & 3;
    #pragma unroll
    for (int mi = 0; mi < 2; ++mi) {
        int r0 = mbase + m0 + mi * 16 + grp;
        #pragma unroll
        for (int nj = 0; nj < 8; ++nj) {
            int c0 = nbg + nb0 + nj * 8 + qp * 2;
            *(float2*)&Yp[(size_t)r0 * ZC + c0]       = make_float2(acc[mi][nj][0], acc[mi][nj][1]);
            *(float2*)&Yp[(size_t)(r0 + 8) * ZC + c0] = make_float2(acc[mi][nj][2], acc[mi][nj][3]);
        }
    }
}

// ---------------------------------------------------------------------------
// K4: epilogue. Sum 4 partials, s-scale + diag, write out, BN stats.
// 1024 blocks x 256 thr; thread handles one float4 (row i, cols C..C+3).
// ---------------------------------------------------------------------------
__global__ void k_epi(float* __restrict__ out) {
    __shared__ float sstat[2 * DD];
    int t = threadIdx.x;
    sstat[t] = 0.0f;
    __syncthreads();
    int gid = blockIdx.x * 256 + t;          // over 4096*64 float4 groups
    int i = gid >> 6;
    int C = (gid & 63) * 4;
    float4 y = *(const float4*)&g_Yp[0][(size_t)i * ZC + C];
    #pragma unroll
    for (int z = 1; z < KSPLIT; ++z) {
        float4 p = *(const float4*)&g_Yp[z][(size_t)i * ZC + C];
        y.x += p.x; y.y += p.y; y.z += p.z; y.w += p.w;
    }
    float s = g_s[i], s2 = s * s;
    int orow, oc, drow;
    if (C < DD) { orow = i; oc = C; drow = NN + i; }
    else        { orow = NN + i; oc = C - DD; drow = i; }
    float4 d = *(const float4*)&g_XW[(size_t)drow * DD + oc];
    float4 h;
    h.x = s * y.x + s2 * d.x; h.y = s * y.y + s2 * d.y;
    h.z = s * y.z + s2 * d.z; h.w = s * y.w + s2 * d.w;
    *(float4*)&out[(size_t)orow * DD + oc] = h;
    atomicAdd(&sstat[oc + 0], h.x); atomicAdd(&sstat[DD + oc + 0], h.x * h.x);
    atomicAdd(&sstat[oc + 1], h.y); atomicAdd(&sstat[DD + oc + 1], h.y * h.y);
    atomicAdd(&sstat[oc + 2], h.z); atomicAdd(&sstat[DD + oc + 2], h.z * h.z);
    atomicAdd(&sstat[oc + 3], h.w); atomicAdd(&sstat[DD + oc + 3], h.w * h.w);
    __syncthreads();
    atomicAdd(&g_stats[t], sstat[t]);
}

// ---------------------------------------------------------------------------
// K5: finalize BatchNorm (biased var) + ReLU in place
// ---------------------------------------------------------------------------
__global__ void k_bn(float* __restrict__ out,
                     const float* __restrict__ gamma,
                     const float* __restrict__ beta) {
    __shared__ float sscale[DD], sshift[DD];
    if (threadIdx.x < DD) {
        int c = threadIdx.x;
        float mean = g_stats[c] * (1.0f / (float)TWO_N);
        float var  = g_stats[DD + c] * (1.0f / (float)TWO_N) - mean * mean;
        float inv  = rsqrtf(var + 1e-5f);
        float g = gamma[c];
        sscale[c] = inv * g;
        sshift[c] = beta[c] - mean * inv * g;
    }
    __syncthreads();
    int idx = blockIdx.x * 256 + threadIdx.x;
    int c = idx & (DD - 1);
    float v = out[idx] * sscale[c] + sshift[c];
    out[idx] = fmaxf(v, 0.0f);
}

// ---------------------------------------------------------------------------
extern "C" void kernel_launch(void* const* d_in, const int* in_sizes, int n_in,
                              void* d_out, int out_size) {
    const float* x     = (const float*)d_in[0];   // [8192, 128]
    const float* A     = (const float*)d_in[1];   // [4096, 4096]
    const float* Wm    = (const float*)d_in[2];   // [128, 128]
    const float* gamma = (const float*)d_in[3];   // [128]
    const float* beta  = (const float*)d_in[4];   // [128]
    float* out = (float*)d_out;                   // [8192, 128]

    cudaFuncSetAttribute(k_gemm, cudaFuncAttributeMaxDynamicSharedMemorySize, SMEM_GEMM);

    k_prep<<<NN, 128>>>(A);
    k_xw2 <<<NN / 32, 256>>>(x, Wm);
    dim3 gg(NN / 128, 2, KSPLIT);
    k_gemm<<<gg, 256, SMEM_GEMM>>>();
    k_epi <<<1024, 256>>>(out);
    k_bn  <<<(TWO_N * DD) / 256, 256>>>(out, gamma, beta);
}

// round 5
// speedup vs baseline: 5.1099x; 1.0283x over previous
#include <cuda_runtime.h>
#include <cuda_bf16.h>
#include <cstdint>

#define NN    4096
#define DD    128
#define TWO_N 8192
#define ZC    256
#define KSPLIT 2
#define KPER  (NN / KSPLIT)      // 2048 per CTA
#define KC    64
#define NCHC  (KPER / KC)        // 32 chunks
#define NT    64                 // N tile
#define STG   32768              // A 16K + Bhi 8K + Blo 8K
#define SMEM_GEMM (3 * STG)      // 98304 -> 2 CTAs/SM

// ------------------------- device scratch -------------------------
__device__ __align__(16) __nv_bfloat16 g_Abf[(size_t)NN * NN];   // 32 MB
__device__ __align__(16) __nv_bfloat16 g_Zhi[(size_t)NN * ZC];   // 2 MB [K][N]
__device__ __align__(16) __nv_bfloat16 g_Zlo[(size_t)NN * ZC];   // 2 MB
__device__ __align__(16) float g_XW[(size_t)TWO_N * DD];         // 4 MB
__device__ __align__(16) float g_Yp[KSPLIT][(size_t)NN * ZC];    // 8 MB partials
__device__ float g_s[NN];
__device__ float g_stats[2 * DD];

// ------------------------- PTX helpers ----------------------------
__device__ __forceinline__ uint32_t smem_u32(const void* p) {
    uint32_t a;
    asm("{ .reg .u64 t; cvta.to.shared.u64 t, %1; cvt.u32.u64 %0, t; }" : "=r"(a) : "l"(p));
    return a;
}
#define CP16(dst, src) asm volatile("cp.async.cg.shared.global [%0], [%1], 16;" :: "r"(dst), "l"(src))
#define CP_COMMIT()    asm volatile("cp.async.commit_group;" ::: "memory")
#define CP_WAIT1()     asm volatile("cp.async.wait_group 1;" ::: "memory")

#define LDSM4(r, a)  asm volatile("ldmatrix.sync.aligned.m8n8.x4.shared.b16 {%0,%1,%2,%3}, [%4];" \
    : "=r"((r)[0]),"=r"((r)[1]),"=r"((r)[2]),"=r"((r)[3]) : "r"(a))
#define LDSM4T(r, a) asm volatile("ldmatrix.sync.aligned.m8n8.x4.trans.shared.b16 {%0,%1,%2,%3}, [%4];" \
    : "=r"((r)[0]),"=r"((r)[1]),"=r"((r)[2]),"=r"((r)[3]) : "r"(a))

#define MMA(d, a, b0_, b1_) asm volatile( \
    "mma.sync.aligned.m16n8k16.row.col.f32.bf16.bf16.f32 " \
    "{%0,%1,%2,%3},{%4,%5,%6,%7},{%8,%9},{%0,%1,%2,%3};" \
    : "+f"((d)[0]),"+f"((d)[1]),"+f"((d)[2]),"+f"((d)[3]) \
    : "r"((a)[0]),"r"((a)[1]),"r"((a)[2]),"r"((a)[3]), "r"(b0_), "r"(b1_))

// ---------------------------------------------------------------------------
// K1: binarize A -> bf16 row-major, rowsum -> s, zero stats.
// ---------------------------------------------------------------------------
__global__ void k_prep(const float* __restrict__ A) {
    int row = blockIdx.x, t = threadIdx.x, w = t >> 5, l = t & 31;
    __shared__ int scnt[4];
    if (row == 0 && t < 128) { g_stats[t] = 0.0f; g_stats[128 + t] = 0.0f; }
    const float4* ar4 = (const float4*)(A + (size_t)row * NN);
    uint2* dst = (uint2*)(g_Abf + (size_t)row * NN);
    int cnt = 0;
    #pragma unroll
    for (int it = 0; it < 8; ++it) {
        int i4 = it * 128 + t;
        float4 v = ar4[i4];
        unsigned b0 = (v.x > 0.f) ? 0x3F80u : 0u;
        unsigned b1 = (v.y > 0.f) ? 0x3F80u : 0u;
        unsigned b2 = (v.z > 0.f) ? 0x3F80u : 0u;
        unsigned b3 = (v.w > 0.f) ? 0x3F80u : 0u;
        cnt += (b0 ? 1 : 0) + (b1 ? 1 : 0) + (b2 ? 1 : 0) + (b3 ? 1 : 0);
        uint2 pk; pk.x = b0 | (b1 << 16); pk.y = b2 | (b3 << 16);
        dst[i4] = pk;
    }
    #pragma unroll
    for (int o = 16; o; o >>= 1) cnt += __shfl_down_sync(0xffffffffu, cnt, o);
    if (l == 0) scnt[w] = cnt;
    __syncthreads();
    if (t == 0)
        g_s[row] = rsqrtf((float)(scnt[0] + scnt[1] + scnt[2] + scnt[3] + 1));
}

// ---------------------------------------------------------------------------
// K2: fused xw = x@W and Z build (hi/lo bf16 rows).
// ---------------------------------------------------------------------------
__global__ void k_xw2(const float* __restrict__ x, const float* __restrict__ W) {
    __shared__ float xs[64][128];
    int t = threadIdx.x, w = t >> 5, l = t & 31;
    int j0 = blockIdx.x * 32;
    const float4* xt = (const float4*)(x + (size_t)j0 * DD);
    const float4* xb = (const float4*)(x + (size_t)(NN + j0) * DD);
    float4* xs4 = (float4*)xs;
    #pragma unroll
    for (int i = 0; i < 4; ++i) xs4[t + i * 256] = xt[t + i * 256];
    #pragma unroll
    for (int i = 0; i < 4; ++i) xs4[1024 + t + i * 256] = xb[t + i * 256];
    __syncthreads();
    const float4* W4 = (const float4*)W;
    float acc[8][4];
    #pragma unroll
    for (int i = 0; i < 8; ++i) { acc[i][0]=0.f; acc[i][1]=0.f; acc[i][2]=0.f; acc[i][3]=0.f; }
    #pragma unroll 4
    for (int k = 0; k < DD; ++k) {
        float4 wv = W4[k * 32 + l];
        #pragma unroll
        for (int i = 0; i < 8; ++i) {
            float u = xs[w * 8 + i][k];
            acc[i][0] += u * wv.x; acc[i][1] += u * wv.y;
            acc[i][2] += u * wv.z; acc[i][3] += u * wv.w;
        }
    }
    #pragma unroll
    for (int i = 0; i < 8; ++i) {
        int r = w * 8 + i;
        int top = (r < 32);
        int j = j0 + (r & 31);
        int grow = top ? j : (NN + j);
        float4 v = make_float4(acc[i][0], acc[i][1], acc[i][2], acc[i][3]);
        *(float4*)&g_XW[(size_t)grow * DD + 4 * l] = v;
        float s = g_s[j];
        float z0 = s * v.x, z1 = s * v.y, z2 = s * v.z, z3 = s * v.w;
        __nv_bfloat16 h0 = __float2bfloat16(z0), h1 = __float2bfloat16(z1);
        __nv_bfloat16 h2 = __float2bfloat16(z2), h3 = __float2bfloat16(z3);
        __nv_bfloat16 e0 = __float2bfloat16(z0 - __bfloat162float(h0));
        __nv_bfloat16 e1 = __float2bfloat16(z1 - __bfloat162float(h1));
        __nv_bfloat16 e2 = __float2bfloat16(z2 - __bfloat162float(h2));
        __nv_bfloat16 e3 = __float2bfloat16(z3 - __bfloat162float(h3));
        uint2 hp, lp;
        hp.x = (unsigned)__bfloat16_as_ushort(h0) | ((unsigned)__bfloat16_as_ushort(h1) << 16);
        hp.y = (unsigned)__bfloat16_as_ushort(h2) | ((unsigned)__bfloat16_as_ushort(h3) << 16);
        lp.x = (unsigned)__bfloat16_as_ushort(e0) | ((unsigned)__bfloat16_as_ushort(e1) << 16);
        lp.y = (unsigned)__bfloat16_as_ushort(e2) | ((unsigned)__bfloat16_as_ushort(e3) << 16);
        int coff = (top ? 0 : DD) + 4 * l;
        *(uint2*)&g_Zhi[(size_t)j * ZC + coff] = hp;
        *(uint2*)&g_Zlo[(size_t)j * ZC + coff] = lp;
    }
}

// ---------------------------------------------------------------------------
// K3: GEMM partials. grid (32, 4, 2): tile 128x64, K-split/2 over grid.z.
// 3-stage cp.async pipeline, ONE __syncthreads per chunk. 2 CTAs/SM.
// 8 warps, warp tile 32x32 (acc = 32 regs).
// ---------------------------------------------------------------------------
__global__ void __launch_bounds__(256, 2) k_gemm() {
    extern __shared__ char smem[];
    uint32_t sb = smem_u32(smem);
    int t = threadIdx.x, wid = t >> 5, lid = t & 31;
    int wm = wid & 3, wn = wid >> 2;
    int m0 = wm * 32, nb0 = wn * 32;
    int mbase = blockIdx.x * 128;
    int nbg   = blockIdx.y * NT;
    int kbase = blockIdx.z * KPER;
    const __nv_bfloat16* Ag = g_Abf + (size_t)mbase * NN + kbase;
    const __nv_bfloat16* Bh = g_Zhi + (size_t)kbase * ZC + nbg;
    const __nv_bfloat16* Bl = g_Zlo + (size_t)kbase * ZC + nbg;

    auto issue = [&](int c) {
        if (c < NCHC) {
            uint32_t sa = sb + (c % 3) * STG;
            uint32_t bh = sa + 16384, bl = sa + 24576;
            #pragma unroll
            for (int p = 0; p < 4; ++p) {            // A: 128x64 bf16, 128B rows
                int idx = t + p * 256;
                int r = idx >> 3, ch = idx & 7;
                uint32_t d = sa + r * 128 + ((ch ^ (r & 7)) << 4);
                CP16(d, (const char*)(Ag + (size_t)r * NN + c * KC + ch * 8));
            }
            #pragma unroll
            for (int p = 0; p < 2; ++p) {            // Bhi: 64x64 bf16, 128B rows
                int idx = t + p * 256;
                int k = idx >> 3, ch = idx & 7;
                uint32_t off = k * 128 + ((ch ^ (k & 7)) << 4);
                CP16(bh + off, (const char*)(Bh + (size_t)(c * KC + k) * ZC + ch * 8));
            }
            #pragma unroll
            for (int p = 0; p < 2; ++p) {            // Blo
                int idx = t + p * 256;
                int k = idx >> 3, ch = idx & 7;
                uint32_t off = k * 128 + ((ch ^ (k & 7)) << 4);
                CP16(bl + off, (const char*)(Bl + (size_t)(c * KC + k) * ZC + ch * 8));
            }
        }
        CP_COMMIT();
    };

    float acc[2][4][4];
    #pragma unroll
    for (int mi = 0; mi < 2; ++mi)
        #pragma unroll
        for (int nj = 0; nj < 4; ++nj)
            #pragma unroll
            for (int q = 0; q < 4; ++q) acc[mi][nj][q] = 0.0f;

    issue(0); issue(1);

    for (int c = 0; c < NCHC; ++c) {
        CP_WAIT1();                  // chunk c resident
        __syncthreads();             // all warps done with chunk c-1
        issue(c + 2);                // fills stage (c+2)%3 == (c-1)%3 (free)
        uint32_t sa = sb + (c % 3) * STG;
        uint32_t bhb = sa + 16384, blb = sa + 24576;
        #pragma unroll
        for (int kk = 0; kk < 4; ++kk) {
            uint32_t af[2][4];
            #pragma unroll
            for (int mi = 0; mi < 2; ++mi) {
                int row = m0 + mi * 16 + (lid & 15);
                int ch  = kk * 2 + (lid >> 4);
                LDSM4(af[mi], sa + row * 128 + ((ch ^ (row & 7)) << 4));
            }
            int kb = kk * 16 + (lid & 15);
            int cb = lid >> 4;
            uint32_t bf[4][2];
            #pragma unroll
            for (int np = 0; np < 2; ++np) {         // hi: 32 cols
                int ch = (nb0 >> 3) + np * 2 + cb;
                uint32_t r4[4];
                LDSM4T(r4, bhb + kb * 128 + ((ch ^ (kb & 7)) << 4));
                bf[np*2][0]=r4[0]; bf[np*2][1]=r4[1]; bf[np*2+1][0]=r4[2]; bf[np*2+1][1]=r4[3];
            }
            #pragma unroll
            for (int mi = 0; mi < 2; ++mi)
                #pragma unroll
                for (int nj = 0; nj < 4; ++nj)
                    MMA(acc[mi][nj], af[mi], bf[nj][0], bf[nj][1]);
            #pragma unroll
            for (int np = 0; np < 2; ++np) {         // lo
                int ch = (nb0 >> 3) + np * 2 + cb;
                uint32_t r4[4];
                LDSM4T(r4, blb + kb * 128 + ((ch ^ (kb & 7)) << 4));
                bf[np*2][0]=r4[0]; bf[np*2][1]=r4[1]; bf[np*2+1][0]=r4[2]; bf[np*2+1][1]=r4[3];
            }
            #pragma unroll
            for (int mi = 0; mi < 2; ++mi)
                #pragma unroll
                for (int nj = 0; nj < 4; ++nj)
                    MMA(acc[mi][nj], af[mi], bf[nj][0], bf[nj][1]);
        }
    }

    // write partial tile
    float* Yp = g_Yp[blockIdx.z];
    int grp = lid >> 2, qp = lid & 3;
    #pragma unroll
    for (int mi = 0; mi < 2; ++mi) {
        int r0 = mbase + m0 + mi * 16 + grp;
        #pragma unroll
        for (int nj = 0; nj < 4; ++nj) {
            int c0 = nbg + nb0 + nj * 8 + qp * 2;
            *(float2*)&Yp[(size_t)r0 * ZC + c0]       = make_float2(acc[mi][nj][0], acc[mi][nj][1]);
            *(float2*)&Yp[(size_t)(r0 + 8) * ZC + c0] = make_float2(acc[mi][nj][2], acc[mi][nj][3]);
        }
    }
}

// ---------------------------------------------------------------------------
// K4: epilogue. Sum partials, s-scale + diag, write out, BN stats with
// register-local accumulation (column-invariant striding) -> few atomics.
// ---------------------------------------------------------------------------
__global__ void k_epi(float* __restrict__ out) {
    __shared__ float sstat[2 * DD];
    int t = threadIdx.x;
    sstat[t] = 0.0f;
    __syncthreads();
    int base = blockIdx.x * 256 + t;            // slots strided by 65536 (4 per thread)
    int C = (base & 63) * 4;                    // invariant across s
    float lsum[4] = {0.f, 0.f, 0.f, 0.f};
    float lsq[4]  = {0.f, 0.f, 0.f, 0.f};
    int oc = (C < DD) ? C : (C - DD);
    #pragma unroll
    for (int sIt = 0; sIt < 4; ++sIt) {
        int slot = base + sIt * 65536;
        int i = slot >> 6;
        float4 y0 = *(const float4*)&g_Yp[0][(size_t)i * ZC + C];
        float4 y1 = *(const float4*)&g_Yp[1][(size_t)i * ZC + C];
        float4 y; y.x = y0.x + y1.x; y.y = y0.y + y1.y; y.z = y0.z + y1.z; y.w = y0.w + y1.w;
        float s = g_s[i], s2 = s * s;
        int orow, drow;
        if (C < DD) { orow = i; drow = NN + i; }
        else        { orow = NN + i; drow = i; }
        float4 d = *(const float4*)&g_XW[(size_t)drow * DD + oc];
        float4 h;
        h.x = s * y.x + s2 * d.x; h.y = s * y.y + s2 * d.y;
        h.z = s * y.z + s2 * d.z; h.w = s * y.w + s2 * d.w;
        *(float4*)&out[(size_t)orow * DD + oc] = h;
        lsum[0] += h.x; lsum[1] += h.y; lsum[2] += h.z; lsum[3] += h.w;
        lsq[0] += h.x * h.x; lsq[1] += h.y * h.y; lsq[2] += h.z * h.z; lsq[3] += h.w * h.w;
    }
    #pragma unroll
    for (int q = 0; q < 4; ++q) {
        atomicAdd(&sstat[oc + q], lsum[q]);
        atomicAdd(&sstat[DD + oc + q], lsq[q]);
    }
    __syncthreads();
    atomicAdd(&g_stats[t], sstat[t]);
}

// ---------------------------------------------------------------------------
// K5: finalize BatchNorm (biased var) + ReLU in place
// ---------------------------------------------------------------------------
__global__ void k_bn(float* __restrict__ out,
                     const float* __restrict__ gamma,
                     const float* __restrict__ beta) {
    __shared__ float sscale[DD], sshift[DD];
    if (threadIdx.x < DD) {
        int c = threadIdx.x;
        float mean = g_stats[c] * (1.0f / (float)TWO_N);
        float var  = g_stats[DD + c] * (1.0f / (float)TWO_N) - mean * mean;
        float inv  = rsqrtf(var + 1e-5f);
        float g = gamma[c];
        sscale[c] = inv * g;
        sshift[c] = beta[c] - mean * inv * g;
    }
    __syncthreads();
    int idx = blockIdx.x * 256 + threadIdx.x;
    int c = idx & (DD - 1);
    float v = out[idx] * sscale[c] + sshift[c];
    out[idx] = fmaxf(v, 0.0f);
}

// ---------------------------------------------------------------------------
extern "C" void kernel_launch(void* const* d_in, const int* in_sizes, int n_in,
                              void* d_out, int out_size) {
    const float* x     = (const float*)d_in[0];   // [8192, 128]
    const float* A     = (const float*)d_in[1];   // [4096, 4096]
    const float* Wm    = (const float*)d_in[2];   // [128, 128]
    const float* gamma = (const float*)d_in[3];   // [128]
    const float* beta  = (const float*)d_in[4];   // [128]
    float* out = (float*)d_out;                   // [8192, 128]

    cudaFuncSetAttribute(k_gemm, cudaFuncAttributeMaxDynamicSharedMemorySize, SMEM_GEMM);

    k_prep<<<NN, 128>>>(A);
    k_xw2 <<<NN / 32, 256>>>(x, Wm);
    dim3 gg(NN / 128, ZC / NT, KSPLIT);
    k_gemm<<<gg, 256, SMEM_GEMM>>>();
    k_epi <<<256, 256>>>(out);
    k_bn  <<<(TWO_N * DD) / 256, 256>>>(out, gamma, beta);
}

// round 6
// speedup vs baseline: 6.2288x; 1.2190x over previous
#include <cuda_runtime.h>
#include <cuda_fp16.h>
#include <cstdint>

#define NN    4096
#define DD    128
#define TWO_N 8192
#define ZC    256
#define KSPLIT 4
#define KPER  (NN / KSPLIT)      // 1024 per CTA
#define KC    64
#define NCHC  (KPER / KC)        // 16 chunks
#define NT    128                // N tile
#define STG   32768              // A 16K + B 16K
#define SMEM_GEMM (3 * STG)      // 98304 -> 2 CTAs/SM

// ------------------------- device scratch -------------------------
__device__ __align__(16) __half g_Ah[(size_t)NN * NN];           // 32 MB fp16
__device__ __align__(16) __half g_Zh[(size_t)NN * ZC];           // 2 MB  [K][N] fp16
__device__ __align__(16) float g_XW[(size_t)TWO_N * DD];         // 4 MB
__device__ __align__(16) float g_Yp[KSPLIT][(size_t)NN * ZC];    // 16 MB partials
__device__ float g_s[NN];
__device__ float g_stats[2 * DD];

// ------------------------- PTX helpers ----------------------------
__device__ __forceinline__ uint32_t smem_u32(const void* p) {
    uint32_t a;
    asm("{ .reg .u64 t; cvta.to.shared.u64 t, %1; cvt.u32.u64 %0, t; }" : "=r"(a) : "l"(p));
    return a;
}
#define CP16(dst, src) asm volatile("cp.async.cg.shared.global [%0], [%1], 16;" :: "r"(dst), "l"(src))
#define CP_COMMIT()    asm volatile("cp.async.commit_group;" ::: "memory")
#define CP_WAIT1()     asm volatile("cp.async.wait_group 1;" ::: "memory")

#define LDSM4(r, a)  asm volatile("ldmatrix.sync.aligned.m8n8.x4.shared.b16 {%0,%1,%2,%3}, [%4];" \
    : "=r"((r)[0]),"=r"((r)[1]),"=r"((r)[2]),"=r"((r)[3]) : "r"(a))
#define LDSM4T(r, a) asm volatile("ldmatrix.sync.aligned.m8n8.x4.trans.shared.b16 {%0,%1,%2,%3}, [%4];" \
    : "=r"((r)[0]),"=r"((r)[1]),"=r"((r)[2]),"=r"((r)[3]) : "r"(a))

#define MMA(d, a, b0_, b1_) asm volatile( \
    "mma.sync.aligned.m16n8k16.row.col.f32.f16.f16.f32 " \
    "{%0,%1,%2,%3},{%4,%5,%6,%7},{%8,%9},{%0,%1,%2,%3};" \
    : "+f"((d)[0]),"+f"((d)[1]),"+f"((d)[2]),"+f"((d)[3]) \
    : "r"((a)[0]),"r"((a)[1]),"r"((a)[2]),"r"((a)[3]), "r"(b0_), "r"(b1_))

// ---------------------------------------------------------------------------
// K1: binarize A -> fp16 row-major (1.0/0.0), rowsum -> s, zero stats.
// ---------------------------------------------------------------------------
__global__ void k_prep(const float* __restrict__ A) {
    int row = blockIdx.x, t = threadIdx.x, w = t >> 5, l = t & 31;
    __shared__ int scnt[4];
    if (row == 0 && t < 128) { g_stats[t] = 0.0f; g_stats[128 + t] = 0.0f; }
    const float4* ar4 = (const float4*)(A + (size_t)row * NN);
    uint2* dst = (uint2*)(g_Ah + (size_t)row * NN);
    int cnt = 0;
    #pragma unroll
    for (int it = 0; it < 8; ++it) {
        int i4 = it * 128 + t;
        float4 v = ar4[i4];
        unsigned b0 = (v.x > 0.f) ? 0x3C00u : 0u;     // fp16 1.0
        unsigned b1 = (v.y > 0.f) ? 0x3C00u : 0u;
        unsigned b2 = (v.z > 0.f) ? 0x3C00u : 0u;
        unsigned b3 = (v.w > 0.f) ? 0x3C00u : 0u;
        cnt += (b0 ? 1 : 0) + (b1 ? 1 : 0) + (b2 ? 1 : 0) + (b3 ? 1 : 0);
        uint2 pk; pk.x = b0 | (b1 << 16); pk.y = b2 | (b3 << 16);
        dst[i4 >> 1] = (i4 & 1) ? pk : pk;            // placeholder (replaced below)
    }
    // NOTE: the store above must pack two float4->4 halves = 8 bytes at half-rate
    // index; redo correctly: each i4 covers 4 elements = 8 bytes = one uint2 slot.
    // dst is uint2* over fp16 row: element i4 -> byte offset i4*8 -> dst[i4]. Fixed:
    #pragma unroll
    for (int o = 16; o; o >>= 1) cnt += __shfl_down_sync(0xffffffffu, cnt, o);
    if (l == 0) scnt[w] = cnt;
    __syncthreads();
    if (t == 0)
        g_s[row] = rsqrtf((float)(scnt[0] + scnt[1] + scnt[2] + scnt[3] + 1));
}

// Correct standalone prep store (the kernel above had an indexing slip; this
// version is the one actually launched).
__global__ void k_prep2(const float* __restrict__ A) {
    int row = blockIdx.x, t = threadIdx.x, w = t >> 5, l = t & 31;
    __shared__ int scnt[4];
    if (row == 0 && t < 128) { g_stats[t] = 0.0f; g_stats[128 + t] = 0.0f; }
    const float4* ar4 = (const float4*)(A + (size_t)row * NN);
    uint2* dst = (uint2*)(g_Ah + (size_t)row * NN);   // uint2 = 4 halves
    int cnt = 0;
    #pragma unroll
    for (int it = 0; it < 8; ++it) {
        int i4 = it * 128 + t;                        // float4 group index, 0..1023
        float4 v = ar4[i4];
        unsigned b0 = (v.x > 0.f) ? 0x3C00u : 0u;
        unsigned b1 = (v.y > 0.f) ? 0x3C00u : 0u;
        unsigned b2 = (v.z > 0.f) ? 0x3C00u : 0u;
        unsigned b3 = (v.w > 0.f) ? 0x3C00u : 0u;
        cnt += (b0 ? 1 : 0) + (b1 ? 1 : 0) + (b2 ? 1 : 0) + (b3 ? 1 : 0);
        uint2 pk; pk.x = b0 | (b1 << 16); pk.y = b2 | (b3 << 16);
        dst[i4] = pk;                                 // 4 halves = 8 bytes
    }
    #pragma unroll
    for (int o = 16; o; o >>= 1) cnt += __shfl_down_sync(0xffffffffu, cnt, o);
    if (l == 0) scnt[w] = cnt;
    __syncthreads();
    if (t == 0)
        g_s[row] = rsqrtf((float)(scnt[0] + scnt[1] + scnt[2] + scnt[3] + 1));
}

// ---------------------------------------------------------------------------
// K2: fused xw = x@W and Z build (fp16 rows).
// ---------------------------------------------------------------------------
__global__ void k_xw2(const float* __restrict__ x, const float* __restrict__ W) {
    __shared__ float xs[64][128];
    int t = threadIdx.x, w = t >> 5, l = t & 31;
    int j0 = blockIdx.x * 32;
    const float4* xt = (const float4*)(x + (size_t)j0 * DD);
    const float4* xb = (const float4*)(x + (size_t)(NN + j0) * DD);
    float4* xs4 = (float4*)xs;
    #pragma unroll
    for (int i = 0; i < 4; ++i) xs4[t + i * 256] = xt[t + i * 256];
    #pragma unroll
    for (int i = 0; i < 4; ++i) xs4[1024 + t + i * 256] = xb[t + i * 256];
    __syncthreads();
    const float4* W4 = (const float4*)W;
    float acc[8][4];
    #pragma unroll
    for (int i = 0; i < 8; ++i) { acc[i][0]=0.f; acc[i][1]=0.f; acc[i][2]=0.f; acc[i][3]=0.f; }
    #pragma unroll 4
    for (int k = 0; k < DD; ++k) {
        float4 wv = W4[k * 32 + l];
        #pragma unroll
        for (int i = 0; i < 8; ++i) {
            float u = xs[w * 8 + i][k];
            acc[i][0] += u * wv.x; acc[i][1] += u * wv.y;
            acc[i][2] += u * wv.z; acc[i][3] += u * wv.w;
        }
    }
    #pragma unroll
    for (int i = 0; i < 8; ++i) {
        int r = w * 8 + i;
        int top = (r < 32);
        int j = j0 + (r & 31);
        int grow = top ? j : (NN + j);
        float4 v = make_float4(acc[i][0], acc[i][1], acc[i][2], acc[i][3]);
        *(float4*)&g_XW[(size_t)grow * DD + 4 * l] = v;
        float s = g_s[j];
        __half h0 = __float2half_rn(s * v.x);
        __half h1 = __float2half_rn(s * v.y);
        __half h2 = __float2half_rn(s * v.z);
        __half h3 = __float2half_rn(s * v.w);
        uint2 hp;
        hp.x = (unsigned)__half_as_ushort(h0) | ((unsigned)__half_as_ushort(h1) << 16);
        hp.y = (unsigned)__half_as_ushort(h2) | ((unsigned)__half_as_ushort(h3) << 16);
        int coff = (top ? 0 : DD) + 4 * l;
        *(uint2*)&g_Zh[(size_t)j * ZC + coff] = hp;
    }
}

// ---------------------------------------------------------------------------
// K3: GEMM partials. grid (32, 2, 4): CTA tile 128x128, K-split/4 over grid.z.
// 4 warps, warp tile 64x64. 3-stage cp.async, one __syncthreads per chunk.
// 2 CTAs/SM (96KB smem, 128 threads).
// ---------------------------------------------------------------------------
__global__ void __launch_bounds__(128, 2) k_gemm() {
    extern __shared__ char smem[];
    uint32_t sb = smem_u32(smem);
    int t = threadIdx.x, wid = t >> 5, lid = t & 31;
    int wm = wid & 1, wn = wid >> 1;
    int m0 = wm * 64, nb0 = wn * 64;
    int mbase = blockIdx.x * 128;
    int nbg   = blockIdx.y * NT;
    int kbase = blockIdx.z * KPER;
    const __half* Ag = g_Ah + (size_t)mbase * NN + kbase;
    const __half* Bg = g_Zh + (size_t)kbase * ZC + nbg;

    auto issue = [&](int c) {
        if (c < NCHC) {
            uint32_t sa = sb + (c % 3) * STG;
            uint32_t bsm = sa + 16384;
            #pragma unroll
            for (int p = 0; p < 8; ++p) {            // A: 128x64 fp16, 128B rows
                int idx = t + p * 128;
                int r = idx >> 3, ch = idx & 7;
                uint32_t d = sa + r * 128 + ((ch ^ (r & 7)) << 4);
                CP16(d, (const char*)(Ag + (size_t)r * NN + c * KC + ch * 8));
            }
            #pragma unroll
            for (int p = 0; p < 8; ++p) {            // B: 64x128 fp16, 256B rows
                int idx = t + p * 128;
                int k = idx >> 4, ch = idx & 15;
                uint32_t off = k * 256 + ((ch ^ (k & 7)) << 4);
                CP16(bsm + off, (const char*)(Bg + (size_t)(c * KC + k) * ZC + ch * 8));
            }
        }
        CP_COMMIT();
    };

    float acc[4][8][4];
    #pragma unroll
    for (int mi = 0; mi < 4; ++mi)
        #pragma unroll
        for (int nj = 0; nj < 8; ++nj)
            #pragma unroll
            for (int q = 0; q < 4; ++q) acc[mi][nj][q] = 0.0f;

    issue(0); issue(1);

    for (int c = 0; c < NCHC; ++c) {
        CP_WAIT1();                  // chunk c resident
        __syncthreads();             // all warps done with stage (c-1)%3
        issue(c + 2);                // refill stage (c+2)%3 == (c-1)%3
        uint32_t sa = sb + (c % 3) * STG;
        uint32_t bsm = sa + 16384;
        #pragma unroll
        for (int kk = 0; kk < 4; ++kk) {
            uint32_t af[4][4];
            #pragma unroll
            for (int mi = 0; mi < 4; ++mi) {
                int row = m0 + mi * 16 + (lid & 15);
                int ch  = kk * 2 + (lid >> 4);
                LDSM4(af[mi], sa + row * 128 + ((ch ^ (row & 7)) << 4));
            }
            int kb = kk * 16 + (lid & 15);
            int cb = lid >> 4;
            uint32_t bf[8][2];
            #pragma unroll
            for (int np = 0; np < 4; ++np) {
                int ch = (nb0 >> 3) + np * 2 + cb;
                uint32_t r4[4];
                LDSM4T(r4, bsm + kb * 256 + ((ch ^ (kb & 7)) << 4));
                bf[np*2][0]=r4[0]; bf[np*2][1]=r4[1]; bf[np*2+1][0]=r4[2]; bf[np*2+1][1]=r4[3];
            }
            #pragma unroll
            for (int mi = 0; mi < 4; ++mi)
                #pragma unroll
                for (int nj = 0; nj < 8; ++nj)
                    MMA(acc[mi][nj], af[mi], bf[nj][0], bf[nj][1]);
        }
    }

    // write partial tile
    float* Yp = g_Yp[blockIdx.z];
    int grp = lid >> 2, qp = lid & 3;
    #pragma unroll
    for (int mi = 0; mi < 4; ++mi) {
        int r0 = mbase + m0 + mi * 16 + grp;
        #pragma unroll
        for (int nj = 0; nj < 8; ++nj) {
            int c0 = nbg + nb0 + nj * 8 + qp * 2;
            *(float2*)&Yp[(size_t)r0 * ZC + c0]       = make_float2(acc[mi][nj][0], acc[mi][nj][1]);
            *(float2*)&Yp[(size_t)(r0 + 8) * ZC + c0] = make_float2(acc[mi][nj][2], acc[mi][nj][3]);
        }
    }
}

// ---------------------------------------------------------------------------
// K4: epilogue. Sum partials, s-scale + diag, write out, BN stats.
// ---------------------------------------------------------------------------
__global__ void k_epi(float* __restrict__ out) {
    __shared__ float sstat[2 * DD];
    int t = threadIdx.x;
    sstat[t] = 0.0f;
    __syncthreads();
    int base = blockIdx.x * 256 + t;            // 4 slots/thread, stride 65536
    int C = (base & 63) * 4;                    // column invariant across slots
    float lsum[4] = {0.f, 0.f, 0.f, 0.f};
    float lsq[4]  = {0.f, 0.f, 0.f, 0.f};
    int oc = (C < DD) ? C : (C - DD);
    #pragma unroll
    for (int sIt = 0; sIt < 4; ++sIt) {
        int slot = base + sIt * 65536;
        int i = slot >> 6;
        float4 y = *(const float4*)&g_Yp[0][(size_t)i * ZC + C];
        #pragma unroll
        for (int z = 1; z < KSPLIT; ++z) {
            float4 p = *(const float4*)&g_Yp[z][(size_t)i * ZC + C];
            y.x += p.x; y.y += p.y; y.z += p.z; y.w += p.w;
        }
        float s = g_s[i], s2 = s * s;
        int orow, drow;
        if (C < DD) { orow = i; drow = NN + i; }
        else        { orow = NN + i; drow = i; }
        float4 d = *(const float4*)&g_XW[(size_t)drow * DD + oc];
        float4 h;
        h.x = s * y.x + s2 * d.x; h.y = s * y.y + s2 * d.y;
        h.z = s * y.z + s2 * d.z; h.w = s * y.w + s2 * d.w;
        *(float4*)&out[(size_t)orow * DD + oc] = h;
        lsum[0] += h.x; lsum[1] += h.y; lsum[2] += h.z; lsum[3] += h.w;
        lsq[0] += h.x * h.x; lsq[1] += h.y * h.y; lsq[2] += h.z * h.z; lsq[3] += h.w * h.w;
    }
    #pragma unroll
    for (int q = 0; q < 4; ++q) {
        atomicAdd(&sstat[oc + q], lsum[q]);
        atomicAdd(&sstat[DD + oc + q], lsq[q]);
    }
    __syncthreads();
    atomicAdd(&g_stats[t], sstat[t]);
}

// ---------------------------------------------------------------------------
// K5: finalize BatchNorm (biased var) + ReLU in place
// ---------------------------------------------------------------------------
__global__ void k_bn(float* __restrict__ out,
                     const float* __restrict__ gamma,
                     const float* __restrict__ beta) {
    __shared__ float sscale[DD], sshift[DD];
    if (threadIdx.x < DD) {
        int c = threadIdx.x;
        float mean = g_stats[c] * (1.0f / (float)TWO_N);
        float var  = g_stats[DD + c] * (1.0f / (float)TWO_N) - mean * mean;
        float inv  = rsqrtf(var + 1e-5f);
        float g = gamma[c];
        sscale[c] = inv * g;
        sshift[c] = beta[c] - mean * inv * g;
    }
    __syncthreads();
    int idx = blockIdx.x * 256 + threadIdx.x;
    int c = idx & (DD - 1);
    float v = out[idx] * sscale[c] + sshift[c];
    out[idx] = fmaxf(v, 0.0f);
}

// ---------------------------------------------------------------------------
extern "C" void kernel_launch(void* const* d_in, const int* in_sizes, int n_in,
                              void* d_out, int out_size) {
    const float* x     = (const float*)d_in[0];   // [8192, 128]
    const float* A     = (const float*)d_in[1];   // [4096, 4096]
    const float* Wm    = (const float*)d_in[2];   // [128, 128]
    const float* gamma = (const float*)d_in[3];   // [128]
    const float* beta  = (const float*)d_in[4];   // [128]
    float* out = (float*)d_out;                   // [8192, 128]

    cudaFuncSetAttribute(k_gemm, cudaFuncAttributeMaxDynamicSharedMemorySize, SMEM_GEMM);

    k_prep2<<<NN, 128>>>(A);
    k_xw2  <<<NN / 32, 256>>>(x, Wm);
    dim3 gg(NN / 128, ZC / NT, KSPLIT);
    k_gemm <<<gg, 128, SMEM_GEMM>>>();
    k_epi  <<<256, 256>>>(out);
    k_bn   <<<(TWO_N * DD) / 256, 256>>>(out, gamma, beta);
}

// round 7
// speedup vs baseline: 7.0099x; 1.1254x over previous
#include <cuda_runtime.h>
#include <cuda_fp16.h>
#include <cstdint>

#define NN    4096
#define DD    128
#define TWO_N 8192
#define ZC    256
#define KSPLIT 4
#define KPER  (NN / KSPLIT)      // 1024 per CTA
#define KC    64
#define NCHC  (KPER / KC)        // 16 chunks per CTA
#define NCH_ALL (NN / KC)        // 64 chunks total
#define BSTG  16384              // B stage: 64x128 fp16
#define STG   17408              // B + 1KB mask
#define SMEM_GEMM (3 * STG)      // 52224

// ------------------------- device scratch -------------------------
__device__ __align__(16) unsigned g_maskT[(size_t)NCH_ALL * NN * 2]; // 2 MB [chunk][row][2 words]
__device__ __align__(16) __half g_Zh[(size_t)NN * ZC];               // 2 MB [K][N]
__device__ __align__(16) float g_XW[(size_t)TWO_N * DD];             // 4 MB
__device__ __align__(16) float g_Yp[KSPLIT][(size_t)NN * ZC];        // 16 MB partials
__device__ float g_s[NN];
__device__ float g_stats[2 * DD];

// ------------------------- PTX helpers ----------------------------
__device__ __forceinline__ uint32_t smem_u32(const void* p) {
    uint32_t a;
    asm("{ .reg .u64 t; cvta.to.shared.u64 t, %1; cvt.u32.u64 %0, t; }" : "=r"(a) : "l"(p));
    return a;
}
#define CP16(dst, src) asm volatile("cp.async.cg.shared.global [%0], [%1], 16;" :: "r"(dst), "l"(src))
#define CP8(dst, src)  asm volatile("cp.async.ca.shared.global [%0], [%1], 8;"  :: "r"(dst), "l"(src))
#define CP_COMMIT()    asm volatile("cp.async.commit_group;" ::: "memory")
#define CP_WAIT1()     asm volatile("cp.async.wait_group 1;" ::: "memory")

#define LDSM4T(r, a) asm volatile("ldmatrix.sync.aligned.m8n8.x4.trans.shared.b16 {%0,%1,%2,%3}, [%4];" \
    : "=r"((r)[0]),"=r"((r)[1]),"=r"((r)[2]),"=r"((r)[3]) : "r"(a))

#define MMA(d, a, b0_, b1_) asm volatile( \
    "mma.sync.aligned.m16n8k16.row.col.f32.f16.f16.f32 " \
    "{%0,%1,%2,%3},{%4,%5,%6,%7},{%8,%9},{%0,%1,%2,%3};" \
    : "+f"((d)[0]),"+f"((d)[1]),"+f"((d)[2]),"+f"((d)[3]) \
    : "r"((a)[0]),"r"((a)[1]),"r"((a)[2]),"r"((a)[3]), "r"(b0_), "r"(b1_))

// 2 bits -> packed fp16x2 (bit0 -> low half, bit1 -> high half), 1.0 or 0.0
__device__ __forceinline__ uint32_t lut2(unsigned e) {
    return ((e & 1u) ? 0x3C00u : 0u) | ((e & 2u) ? 0x3C000000u : 0u);
}

// ---------------------------------------------------------------------------
// K1: binarize A -> transposed bitmask [chunk][row][2 words]; rowsum -> s.
// Reads A once (64 MB), writes 2 MB. One row per block.
// ---------------------------------------------------------------------------
__global__ void k_prep(const float* __restrict__ A) {
    int row = blockIdx.x, t = threadIdx.x, w = t >> 5, l = t & 31;
    __shared__ int scnt[4];
    if (row == 0 && t < 128) { g_stats[t] = 0.0f; g_stats[128 + t] = 0.0f; }
    const float* ar = A + (size_t)row * NN;
    int cnt = 0;
    #pragma unroll 4
    for (int it = 0; it < 32; ++it) {
        float v = ar[it * 128 + t];
        bool b = (v > 0.0f);
        unsigned bal = __ballot_sync(0xffffffffu, b);
        cnt += b ? 1 : 0;
        if (l == 0) {
            int W = it * 4 + w;                      // 32-col word index 0..127
            g_maskT[((size_t)(W >> 1) * NN + row) * 2 + (W & 1)] = bal;
        }
    }
    #pragma unroll
    for (int o = 16; o; o >>= 1) cnt += __shfl_down_sync(0xffffffffu, cnt, o);
    if (l == 0) scnt[w] = cnt;
    __syncthreads();
    if (t == 0)
        g_s[row] = rsqrtf((float)(scnt[0] + scnt[1] + scnt[2] + scnt[3] + 1));
}

// ---------------------------------------------------------------------------
// K2: fused xw = x@W and Z build (fp16 rows).
// ---------------------------------------------------------------------------
__global__ void k_xw2(const float* __restrict__ x, const float* __restrict__ W) {
    __shared__ float xs[64][128];
    int t = threadIdx.x, w = t >> 5, l = t & 31;
    int j0 = blockIdx.x * 32;
    const float4* xt = (const float4*)(x + (size_t)j0 * DD);
    const float4* xb = (const float4*)(x + (size_t)(NN + j0) * DD);
    float4* xs4 = (float4*)xs;
    #pragma unroll
    for (int i = 0; i < 4; ++i) xs4[t + i * 256] = xt[t + i * 256];
    #pragma unroll
    for (int i = 0; i < 4; ++i) xs4[1024 + t + i * 256] = xb[t + i * 256];
    __syncthreads();
    const float4* W4 = (const float4*)W;
    float acc[8][4];
    #pragma unroll
    for (int i = 0; i < 8; ++i) { acc[i][0]=0.f; acc[i][1]=0.f; acc[i][2]=0.f; acc[i][3]=0.f; }
    #pragma unroll 4
    for (int k = 0; k < DD; ++k) {
        float4 wv = W4[k * 32 + l];
        #pragma unroll
        for (int i = 0; i < 8; ++i) {
            float u = xs[w * 8 + i][k];
            acc[i][0] += u * wv.x; acc[i][1] += u * wv.y;
            acc[i][2] += u * wv.z; acc[i][3] += u * wv.w;
        }
    }
    #pragma unroll
    for (int i = 0; i < 8; ++i) {
        int r = w * 8 + i;
        int top = (r < 32);
        int j = j0 + (r & 31);
        int grow = top ? j : (NN + j);
        float4 v = make_float4(acc[i][0], acc[i][1], acc[i][2], acc[i][3]);
        *(float4*)&g_XW[(size_t)grow * DD + 4 * l] = v;
        float s = g_s[j];
        __half h0 = __float2half_rn(s * v.x);
        __half h1 = __float2half_rn(s * v.y);
        __half h2 = __float2half_rn(s * v.z);
        __half h3 = __float2half_rn(s * v.w);
        uint2 hp;
        hp.x = (unsigned)__half_as_ushort(h0) | ((unsigned)__half_as_ushort(h1) << 16);
        hp.y = (unsigned)__half_as_ushort(h2) | ((unsigned)__half_as_ushort(h3) << 16);
        int coff = (top ? 0 : DD) + 4 * l;
        *(uint2*)&g_Zh[(size_t)j * ZC + coff] = hp;
    }
}

// ---------------------------------------------------------------------------
// K3: GEMM partials. grid (32, 2, 4): CTA tile 128x128, K-split/4 on grid.z.
// A comes from the bitmask: fragments expanded in REGISTERS (no A smem,
// no A ldmatrix, no A gmem fp16 traffic). B via 3-stage cp.async.
// 4 warps, warp tile 64x64. One __syncthreads per chunk. 2 CTAs/SM.
// ---------------------------------------------------------------------------
__global__ void __launch_bounds__(128, 2) k_gemm() {
    extern __shared__ char smem[];
    uint32_t sb = smem_u32(smem);
    int t = threadIdx.x, wid = t >> 5, lid = t & 31;
    int wm = wid & 1, wn = wid >> 1;
    int m0 = wm * 64, nb0 = wn * 64;
    int mbase = blockIdx.x * 128;
    int nbg   = blockIdx.y * 128;
    const __half* Bg = g_Zh + (size_t)(blockIdx.z * KPER) * ZC + nbg;
    const unsigned* Mg = g_maskT + ((size_t)(blockIdx.z * NCHC) * NN + mbase) * 2;

    auto issue = [&](int c) {
        if (c < NCHC) {
            uint32_t sa = sb + (c % 3) * STG;
            #pragma unroll
            for (int p = 0; p < 8; ++p) {            // B: 64x128 fp16, 256B rows
                int idx = t + p * 128;
                int k = idx >> 4, ch = idx & 15;
                uint32_t off = k * 256 + ((ch ^ (k & 7)) << 4);
                CP16(sa + off, (const char*)(Bg + (size_t)(c * KC + k) * ZC + ch * 8));
            }
            // mask: 128 rows x 8B = 1KB contiguous
            CP8(sa + BSTG + t * 8, (const char*)(Mg + (size_t)c * NN * 2 + t * 2));
        }
        CP_COMMIT();
    };

    float acc[4][8][4];
    #pragma unroll
    for (int mi = 0; mi < 4; ++mi)
        #pragma unroll
        for (int nj = 0; nj < 8; ++nj)
            #pragma unroll
            for (int q = 0; q < 4; ++q) acc[mi][nj][q] = 0.0f;

    issue(0); issue(1);

    int ra = lid >> 2;
    int c0 = (lid & 3) * 2;

    for (int c = 0; c < NCHC; ++c) {
        CP_WAIT1();                  // chunk c resident
        __syncthreads();             // all warps done with stage (c-1)%3
        issue(c + 2);                // refills stage (c+2)%3 == (c-1)%3
        uint32_t sa = sb + (c % 3) * STG;
        const uint2* maskS = (const uint2*)(smem + (c % 3) * STG + BSTG);

        uint2 mw0[4], mw1[4];        // mask words for my 8 rows
        #pragma unroll
        for (int mi = 0; mi < 4; ++mi) {
            int rr = m0 + mi * 16 + ra;
            mw0[mi] = maskS[rr];
            mw1[mi] = maskS[rr + 8];
        }

        #pragma unroll
        for (int kk = 0; kk < 4; ++kk) {
            // B fragments
            int kb = kk * 16 + (lid & 15);
            int cb = lid >> 4;
            uint32_t bf[8][2];
            #pragma unroll
            for (int np = 0; np < 4; ++np) {
                int ch = (nb0 >> 3) + np * 2 + cb;
                uint32_t r4[4];
                LDSM4T(r4, sa + kb * 256 + ((ch ^ (kb & 7)) << 4));
                bf[np*2][0]=r4[0]; bf[np*2][1]=r4[1]; bf[np*2+1][0]=r4[2]; bf[np*2+1][1]=r4[3];
            }
            int sh = ((kk & 1) << 4) + c0;
            #pragma unroll
            for (int mi = 0; mi < 4; ++mi) {
                unsigned wa = (kk < 2) ? mw0[mi].x : mw0[mi].y;
                unsigned wb = (kk < 2) ? mw1[mi].x : mw1[mi].y;
                unsigned ta = wa >> sh, tb = wb >> sh;
                uint32_t af[4];
                af[0] = lut2(ta & 3u);          // rows ra,   cols c0..c0+1
                af[1] = lut2(tb & 3u);          // rows ra+8
                af[2] = lut2((ta >> 8) & 3u);   // cols c0+8..c0+9
                af[3] = lut2((tb >> 8) & 3u);
                #pragma unroll
                for (int nj = 0; nj < 8; ++nj)
                    MMA(acc[mi][nj], af, bf[nj][0], bf[nj][1]);
            }
        }
    }

    // write partial tile
    float* Yp = g_Yp[blockIdx.z];
    int grp = lid >> 2, qp = lid & 3;
    #pragma unroll
    for (int mi = 0; mi < 4; ++mi) {
        int r0 = mbase + m0 + mi * 16 + grp;
        #pragma unroll
        for (int nj = 0; nj < 8; ++nj) {
            int cc = nbg + nb0 + nj * 8 + qp * 2;
            *(float2*)&Yp[(size_t)r0 * ZC + cc]       = make_float2(acc[mi][nj][0], acc[mi][nj][1]);
            *(float2*)&Yp[(size_t)(r0 + 8) * ZC + cc] = make_float2(acc[mi][nj][2], acc[mi][nj][3]);
        }
    }
}

// ---------------------------------------------------------------------------
// K4: epilogue. Sum partials, s-scale + diag, write out, BN stats.
// grid 512 x 256, 2 slots/thread (column-invariant striding).
// ---------------------------------------------------------------------------
__global__ void k_epi(float* __restrict__ out) {
    __shared__ float sstat[2 * DD];
    int t = threadIdx.x;
    sstat[t] = 0.0f;
    __syncthreads();
    int base = blockIdx.x * 256 + t;            // 2 slots/thread, stride 131072
    int C = (base & 63) * 4;                    // column invariant across slots
    float lsum[4] = {0.f, 0.f, 0.f, 0.f};
    float lsq[4]  = {0.f, 0.f, 0.f, 0.f};
    int oc = (C < DD) ? C : (C - DD);
    #pragma unroll
    for (int sIt = 0; sIt < 2; ++sIt) {
        int slot = base + sIt * 131072;
        int i = slot >> 6;
        float4 y = *(const float4*)&g_Yp[0][(size_t)i * ZC + C];
        #pragma unroll
        for (int z = 1; z < KSPLIT; ++z) {
            float4 p = *(const float4*)&g_Yp[z][(size_t)i * ZC + C];
            y.x += p.x; y.y += p.y; y.z += p.z; y.w += p.w;
        }
        float s = g_s[i], s2 = s * s;
        int orow, drow;
        if (C < DD) { orow = i; drow = NN + i; }
        else        { orow = NN + i; drow = i; }
        float4 d = *(const float4*)&g_XW[(size_t)drow * DD + oc];
        float4 h;
        h.x = s * y.x + s2 * d.x; h.y = s * y.y + s2 * d.y;
        h.z = s * y.z + s2 * d.z; h.w = s * y.w + s2 * d.w;
        *(float4*)&out[(size_t)orow * DD + oc] = h;
        lsum[0] += h.x; lsum[1] += h.y; lsum[2] += h.z; lsum[3] += h.w;
        lsq[0] += h.x * h.x; lsq[1] += h.y * h.y; lsq[2] += h.z * h.z; lsq[3] += h.w * h.w;
    }
    #pragma unroll
    for (int q = 0; q < 4; ++q) {
        atomicAdd(&sstat[oc + q], lsum[q]);
        atomicAdd(&sstat[DD + oc + q], lsq[q]);
    }
    __syncthreads();
    atomicAdd(&g_stats[t], sstat[t]);
}

// ---------------------------------------------------------------------------
// K5: finalize BatchNorm (biased var) + ReLU in place
// ---------------------------------------------------------------------------
__global__ void k_bn(float* __restrict__ out,
                     const float* __restrict__ gamma,
                     const float* __restrict__ beta) {
    __shared__ float sscale[DD], sshift[DD];
    if (threadIdx.x < DD) {
        int c = threadIdx.x;
        float mean = g_stats[c] * (1.0f / (float)TWO_N);
        float var  = g_stats[DD + c] * (1.0f / (float)TWO_N) - mean * mean;
        float inv  = rsqrtf(var + 1e-5f);
        float g = gamma[c];
        sscale[c] = inv * g;
        sshift[c] = beta[c] - mean * inv * g;
    }
    __syncthreads();
    int idx = blockIdx.x * 256 + threadIdx.x;
    int c = idx & (DD - 1);
    float v = out[idx] * sscale[c] + sshift[c];
    out[idx] = fmaxf(v, 0.0f);
}

// ---------------------------------------------------------------------------
extern "C" void kernel_launch(void* const* d_in, const int* in_sizes, int n_in,
                              void* d_out, int out_size) {
    const float* x     = (const float*)d_in[0];   // [8192, 128]
    const float* A     = (const float*)d_in[1];   // [4096, 4096]
    const float* Wm    = (const float*)d_in[2];   // [128, 128]
    const float* gamma = (const float*)d_in[3];   // [128]
    const float* beta  = (const float*)d_in[4];   // [128]
    float* out = (float*)d_out;                   // [8192, 128]

    cudaFuncSetAttribute(k_gemm, cudaFuncAttributeMaxDynamicSharedMemorySize, SMEM_GEMM);

    k_prep<<<NN, 128>>>(A);
    k_xw2 <<<NN / 32, 256>>>(x, Wm);
    dim3 gg(NN / 128, 2, KSPLIT);
    k_gemm<<<gg, 128, SMEM_GEMM>>>();
    k_epi <<<512, 256>>>(out);
    k_bn  <<<(TWO_N * DD) / 256, 256>>>(out, gamma, beta);
}